// round 9
// baseline (speedup 1.0000x reference)
#include <cuda_runtime.h>
#include <cuda_bf16.h>
#include <cstddef>

// ContinuousGameOfLife: smooth Game-of-Life step on [B=16, H=2048, W=2048] fp32 torus.
// out = f*(1+X);  X = t3 + cell*(t1-t3);  f = 0.25*(1+t2)
//   a1 = 5*around - 7.5; a2 = 10 - a1; a3 = a1 - 5; ti = tanh(ai)
// tanh via single-MUFU tanh.approx; math in packed f32x2.
// R8: horizontal halos via warp shuffle (lane0/31 predicated loads only),
//     streaming stores (__stcs) to keep input resident in L2.

#define GOL_H 2048
#define GOL_W 2048
#define ROWS_PER_THREAD 8

typedef unsigned long long f2;  // packed f32x2 carrier

__device__ __forceinline__ float tanh_fast(float v) {
    float r;
    asm("tanh.approx.f32 %0, %1;" : "=f"(r) : "f"(v));
    return r;
}
__device__ __forceinline__ f2 pk(float lo, float hi) {
    f2 r; asm("mov.b64 %0, {%1, %2};" : "=l"(r) : "f"(lo), "f"(hi)); return r;
}
__device__ __forceinline__ void upk(float& lo, float& hi, f2 v) {
    asm("mov.b64 {%0, %1}, %2;" : "=f"(lo), "=f"(hi) : "l"(v));
}
__device__ __forceinline__ f2 add2(f2 a, f2 b) {
    f2 r; asm("add.rn.f32x2 %0, %1, %2;" : "=l"(r) : "l"(a), "l"(b)); return r;
}
__device__ __forceinline__ f2 sub2(f2 a, f2 b) {
    f2 r; asm("sub.rn.f32x2 %0, %1, %2;" : "=l"(r) : "l"(a), "l"(b)); return r;
}
__device__ __forceinline__ f2 fma2(f2 a, f2 b, f2 c) {
    f2 r; asm("fma.rn.f32x2 %0, %1, %2, %3;" : "=l"(r) : "l"(a), "l"(b), "l"(c)); return r;
}
__device__ __forceinline__ f2 bcast(float c) {
    unsigned int u = __float_as_uint(c);
    return ((f2)u << 32) | (f2)u;
}

// p_lo/p_hi = packed centers; h_lo/h_hi = packed 3-wide horizontal sums
__device__ __forceinline__ void hsum(const float4& m, float l, float r,
                                     f2& p_lo, f2& p_hi, f2& h_lo, f2& h_hi) {
    p_lo = pk(m.x, m.y);
    p_hi = pk(m.z, m.w);
    f2 A = pk(l,   m.x);
    f2 C = pk(m.y, m.z);
    f2 E = pk(m.w, r);
    h_lo = add2(add2(A, p_lo), C);
    h_hi = add2(add2(C, p_hi), E);
}

// Horizontal halo via warp shuffle; only edge lanes touch memory.
__device__ __forceinline__ void halo(const float4& m, const float* rowp,
                                     int xl, int xr, int lane,
                                     float& l, float& r) {
    l = __shfl_up_sync(0xffffffffu,   m.w, 1);
    r = __shfl_down_sync(0xffffffffu, m.x, 1);
    if (lane == 0)  l = __ldg(rowp + xl);
    if (lane == 31) r = __ldg(rowp + xr);
}

__device__ __forceinline__ f2 rule2(f2 cell, f2 H3,
                                    f2 C5, f2 Cm75, f2 C10, f2 C025) {
    f2 ar = sub2(H3, cell);          // around
    f2 a1 = fma2(ar, C5, Cm75);      //  5a - 7.5
    f2 a2 = sub2(C10, a1);           // 17.5 - 5a
    f2 a3 = sub2(a1, C5);            //  5a - 12.5
    float xa, xb;
    upk(xa, xb, a1); f2 t1 = pk(tanh_fast(xa), tanh_fast(xb));
    upk(xa, xb, a2); f2 t2 = pk(tanh_fast(xa), tanh_fast(xb));
    upk(xa, xb, a3); f2 t3 = pk(tanh_fast(xa), tanh_fast(xb));
    f2 d = sub2(t1, t3);
    f2 X = fma2(cell, d, t3);        // t3 + cell*(t1-t3)
    f2 f = fma2(t2, C025, C025);     // 0.25*(1+t2)
    return fma2(X, f, f);            // f*(1+X)
}

__global__ __launch_bounds__(128, 12)
void ContinuousGameOfLife_kernel(const float* __restrict__ x,
                                 float* __restrict__ out) {
    const int W = GOL_W, H = GOL_H;

    const int xb = blockIdx.x * blockDim.x + threadIdx.x;   // 0 .. W/4-1
    const int x4 = xb * 4;
    const int lane = threadIdx.x & 31;
    const int y0 = blockIdx.y * ROWS_PER_THREAD;
    const int b  = blockIdx.z;

    const float* __restrict__ base  = x   + (size_t)b * H * W;
    float*       __restrict__ obase = out + (size_t)b * H * W;

    const int xl = (x4 == 0)     ? (W - 1) : (x4 - 1);
    const int xr = (x4 + 4 == W) ? 0       : (x4 + 4);

    const f2 C5   = bcast(5.0f);
    const f2 Cm75 = bcast(-7.5f);
    const f2 C10  = bcast(10.0f);
    const f2 C025 = bcast(0.25f);

    // ---- prologue: rows y0-1, y0, y0+1 (batched -> MLP) ----
    const int ym = (y0 == 0) ? (H - 1) : (y0 - 1);
    const float* rp0 = base + (size_t)ym * W;
    const float* rp1 = base + (size_t)y0 * W;
    const float* rp2 = base + (size_t)(y0 + 1) * W;
    float4 m0 = *reinterpret_cast<const float4*>(rp0 + x4);
    float4 m1 = *reinterpret_cast<const float4*>(rp1 + x4);
    float4 m2 = *reinterpret_cast<const float4*>(rp2 + x4);
    float l0, r0, l1, r1, l2, r2;
    halo(m0, rp0, xl, xr, lane, l0, r0);
    halo(m1, rp1, xl, xr, lane, l1, r1);
    halo(m2, rp2, xl, xr, lane, l2, r2);

    f2 tmp0, tmp1;
    f2 hP_lo, hP_hi, hC_lo, hC_hi, hN_lo, hN_hi;   // h window rows y-1, y, y+1
    f2 pC_lo, pC_hi, pN_lo, pN_hi;                 // cell packs rows y, y+1
    hsum(m0, l0, r0, tmp0,  tmp1,  hP_lo, hP_hi);
    hsum(m1, l1, r1, pC_lo, pC_hi, hC_lo, hC_hi);
    hsum(m2, l2, r2, pN_lo, pN_hi, hN_lo, hN_hi);

    #pragma unroll
    for (int i = 0; i < ROWS_PER_THREAD; ++i) {
        const int y = y0 + i;

        // -- prefetch row y+2 (wrapped) --
        int yn2 = y + 2; if (yn2 >= H) yn2 -= H;
        const float* rpf = base + (size_t)yn2 * W;
        float4 mf = *reinterpret_cast<const float4*>(rpf + x4);

        // -- compute output row y --
        f2 H3_lo = add2(add2(hP_lo, hC_lo), hN_lo);
        f2 H3_hi = add2(add2(hP_hi, hC_hi), hN_hi);
        f2 o_lo = rule2(pC_lo, H3_lo, C5, Cm75, C10, C025);
        f2 o_hi = rule2(pC_hi, H3_hi, C5, Cm75, C10, C025);

        float4 o;
        upk(o.x, o.y, o_lo);
        upk(o.z, o.w, o_hi);
        __stcs(reinterpret_cast<float4*>(obase + (size_t)y * W + x4), o);

        // -- fold prefetched row into window --
        float lf, rf;
        halo(mf, rpf, xl, xr, lane, lf, rf);
        hP_lo = hC_lo; hP_hi = hC_hi;
        hC_lo = hN_lo; hC_hi = hN_hi;
        pC_lo = pN_lo; pC_hi = pN_hi;
        hsum(mf, lf, rf, pN_lo, pN_hi, hN_lo, hN_hi);
    }
}

extern "C" void kernel_launch(void* const* d_in, const int* in_sizes, int n_in,
                              void* d_out, int out_size) {
    const float* x = (const float*)d_in[0];
    float* out = (float*)d_out;

    const int B = 16;
    dim3 block(128, 1, 1);
    dim3 grid((GOL_W / 4) / 128, GOL_H / ROWS_PER_THREAD, B);
    ContinuousGameOfLife_kernel<<<grid, block>>>(x, out);
}

// round 11
// speedup vs baseline: 1.0992x; 1.0992x over previous
#include <cuda_runtime.h>
#include <cuda_bf16.h>
#include <cstddef>

// ContinuousGameOfLife: smooth Game-of-Life step on [B=16, H=2048, W=2048] fp32 torus.
// out = f*(1+X);  X = t3 + cell*(t1-t3);  f = 0.25*(1+t2)
//   a1 = 5*around - 7.5; a2 = 10 - a1; a3 = a1 - 5; ti = tanh(ai)
// tanh via single-MUFU tanh.approx; math in packed f32x2.
// R9/R11: R6 body (direct halo loads, no shuffle) + streaming stores (__stcs)
//     so the never-re-read output doesn't evict input halo rows from L2.
//     (Resubmission of R9 — R10 was an infra failure, experiment never ran.)

#define GOL_H 2048
#define GOL_W 2048
#define ROWS_PER_THREAD 8

typedef unsigned long long f2;  // packed f32x2 carrier

__device__ __forceinline__ float tanh_fast(float v) {
    float r;
    asm("tanh.approx.f32 %0, %1;" : "=f"(r) : "f"(v));
    return r;
}
__device__ __forceinline__ f2 pk(float lo, float hi) {
    f2 r; asm("mov.b64 %0, {%1, %2};" : "=l"(r) : "f"(lo), "f"(hi)); return r;
}
__device__ __forceinline__ void upk(float& lo, float& hi, f2 v) {
    asm("mov.b64 {%0, %1}, %2;" : "=f"(lo), "=f"(hi) : "l"(v));
}
__device__ __forceinline__ f2 add2(f2 a, f2 b) {
    f2 r; asm("add.rn.f32x2 %0, %1, %2;" : "=l"(r) : "l"(a), "l"(b)); return r;
}
__device__ __forceinline__ f2 sub2(f2 a, f2 b) {
    f2 r; asm("sub.rn.f32x2 %0, %1, %2;" : "=l"(r) : "l"(a), "l"(b)); return r;
}
__device__ __forceinline__ f2 fma2(f2 a, f2 b, f2 c) {
    f2 r; asm("fma.rn.f32x2 %0, %1, %2, %3;" : "=l"(r) : "l"(a), "l"(b), "l"(c)); return r;
}
__device__ __forceinline__ f2 bcast(float c) {
    unsigned int u = __float_as_uint(c);
    return ((f2)u << 32) | (f2)u;
}

// p_lo/p_hi = packed centers; h_lo/h_hi = packed 3-wide horizontal sums
__device__ __forceinline__ void hsum(const float4& m, float l, float r,
                                     f2& p_lo, f2& p_hi, f2& h_lo, f2& h_hi) {
    p_lo = pk(m.x, m.y);
    p_hi = pk(m.z, m.w);
    f2 A = pk(l,   m.x);
    f2 C = pk(m.y, m.z);
    f2 E = pk(m.w, r);
    h_lo = add2(add2(A, p_lo), C);
    h_hi = add2(add2(C, p_hi), E);
}

__device__ __forceinline__ f2 rule2(f2 cell, f2 H3,
                                    f2 C5, f2 Cm75, f2 C10, f2 C025) {
    f2 ar = sub2(H3, cell);          // around
    f2 a1 = fma2(ar, C5, Cm75);      //  5a - 7.5
    f2 a2 = sub2(C10, a1);           // 17.5 - 5a
    f2 a3 = sub2(a1, C5);            //  5a - 12.5
    float xa, xb;
    upk(xa, xb, a1); f2 t1 = pk(tanh_fast(xa), tanh_fast(xb));
    upk(xa, xb, a2); f2 t2 = pk(tanh_fast(xa), tanh_fast(xb));
    upk(xa, xb, a3); f2 t3 = pk(tanh_fast(xa), tanh_fast(xb));
    f2 d = sub2(t1, t3);
    f2 X = fma2(cell, d, t3);        // t3 + cell*(t1-t3)
    f2 f = fma2(t2, C025, C025);     // 0.25*(1+t2)
    return fma2(X, f, f);            // f*(1+X)
}

__global__ __launch_bounds__(128, 12)
void ContinuousGameOfLife_kernel(const float* __restrict__ x,
                                 float* __restrict__ out) {
    const int W = GOL_W, H = GOL_H;

    const int xb = blockIdx.x * blockDim.x + threadIdx.x;   // 0 .. W/4-1
    const int x4 = xb * 4;
    const int y0 = blockIdx.y * ROWS_PER_THREAD;
    const int b  = blockIdx.z;

    const float* __restrict__ base  = x   + (size_t)b * H * W;
    float*       __restrict__ obase = out + (size_t)b * H * W;

    const int xl = (x4 == 0)     ? (W - 1) : (x4 - 1);
    const int xr = (x4 + 4 == W) ? 0       : (x4 + 4);

    const f2 C5   = bcast(5.0f);
    const f2 Cm75 = bcast(-7.5f);
    const f2 C10  = bcast(10.0f);
    const f2 C025 = bcast(0.25f);

    // ---- prologue: rows y0-1, y0, y0+1 (batched -> MLP) ----
    const int ym = (y0 == 0) ? (H - 1) : (y0 - 1);
    const float* rp0 = base + (size_t)ym * W;
    const float* rp1 = base + (size_t)y0 * W;
    const float* rp2 = base + (size_t)(y0 + 1) * W;
    float4 m0 = *reinterpret_cast<const float4*>(rp0 + x4);
    float4 m1 = *reinterpret_cast<const float4*>(rp1 + x4);
    float4 m2 = *reinterpret_cast<const float4*>(rp2 + x4);
    float l0 = rp0[xl], r0 = rp0[xr];
    float l1 = rp1[xl], r1 = rp1[xr];
    float l2 = rp2[xl], r2 = rp2[xr];

    f2 tmp0, tmp1;
    f2 hP_lo, hP_hi, hC_lo, hC_hi, hN_lo, hN_hi;   // h window rows y-1, y, y+1
    f2 pC_lo, pC_hi, pN_lo, pN_hi;                 // cell packs rows y, y+1
    hsum(m0, l0, r0, tmp0,  tmp1,  hP_lo, hP_hi);
    hsum(m1, l1, r1, pC_lo, pC_hi, hC_lo, hC_hi);
    hsum(m2, l2, r2, pN_lo, pN_hi, hN_lo, hN_hi);

    #pragma unroll
    for (int i = 0; i < ROWS_PER_THREAD; ++i) {
        const int y = y0 + i;

        // -- prefetch row y+2 (wrapped) --
        int yn2 = y + 2; if (yn2 >= H) yn2 -= H;
        const float* rpf = base + (size_t)yn2 * W;
        float4 mf = *reinterpret_cast<const float4*>(rpf + x4);
        float lf = rpf[xl], rf = rpf[xr];

        // -- compute output row y --
        f2 H3_lo = add2(add2(hP_lo, hC_lo), hN_lo);
        f2 H3_hi = add2(add2(hP_hi, hC_hi), hN_hi);
        f2 o_lo = rule2(pC_lo, H3_lo, C5, Cm75, C10, C025);
        f2 o_hi = rule2(pC_hi, H3_hi, C5, Cm75, C10, C025);

        float4 o;
        upk(o.x, o.y, o_lo);
        upk(o.z, o.w, o_hi);
        __stcs(reinterpret_cast<float4*>(obase + (size_t)y * W + x4), o);

        // -- fold prefetched row into window --
        hP_lo = hC_lo; hP_hi = hC_hi;
        hC_lo = hN_lo; hC_hi = hN_hi;
        pC_lo = pN_lo; pC_hi = pN_hi;
        hsum(mf, lf, rf, pN_lo, pN_hi, hN_lo, hN_hi);
    }
}

extern "C" void kernel_launch(void* const* d_in, const int* in_sizes, int n_in,
                              void* d_out, int out_size) {
    const float* x = (const float*)d_in[0];
    float* out = (float*)d_out;

    const int B = 16;
    dim3 block(128, 1, 1);
    dim3 grid((GOL_W / 4) / 128, GOL_H / ROWS_PER_THREAD, B);
    ContinuousGameOfLife_kernel<<<grid, block>>>(x, out);
}

// round 12
// speedup vs baseline: 1.1744x; 1.0683x over previous
#include <cuda_runtime.h>
#include <cuda_bf16.h>
#include <cstddef>

// ContinuousGameOfLife: smooth Game-of-Life step on [B=16, H=2048, W=2048] fp32 torus.
// out = f*(1+X);  X = t3 + cell*(t1-t3);  f = 0.25*(1+t2)
//   a1 = 5*around - 7.5; a2 = 10 - a1; a3 = a1 - 5; ti = tanh(ai)
// tanh via single-MUFU tanh.approx; math in packed f32x2.
// R12: ROWS_PER_THREAD=4 (32768 CTAs -> wave-tail loss 8%->3%) and peeled
//      last iteration (removes the dead prefetch+fold: rows loaded R+2, not R+3).

#define GOL_H 2048
#define GOL_W 2048
#define ROWS_PER_THREAD 4

typedef unsigned long long f2;  // packed f32x2 carrier

__device__ __forceinline__ float tanh_fast(float v) {
    float r;
    asm("tanh.approx.f32 %0, %1;" : "=f"(r) : "f"(v));
    return r;
}
__device__ __forceinline__ f2 pk(float lo, float hi) {
    f2 r; asm("mov.b64 %0, {%1, %2};" : "=l"(r) : "f"(lo), "f"(hi)); return r;
}
__device__ __forceinline__ void upk(float& lo, float& hi, f2 v) {
    asm("mov.b64 {%0, %1}, %2;" : "=f"(lo), "=f"(hi) : "l"(v));
}
__device__ __forceinline__ f2 add2(f2 a, f2 b) {
    f2 r; asm("add.rn.f32x2 %0, %1, %2;" : "=l"(r) : "l"(a), "l"(b)); return r;
}
__device__ __forceinline__ f2 sub2(f2 a, f2 b) {
    f2 r; asm("sub.rn.f32x2 %0, %1, %2;" : "=l"(r) : "l"(a), "l"(b)); return r;
}
__device__ __forceinline__ f2 fma2(f2 a, f2 b, f2 c) {
    f2 r; asm("fma.rn.f32x2 %0, %1, %2, %3;" : "=l"(r) : "l"(a), "l"(b), "l"(c)); return r;
}
__device__ __forceinline__ f2 bcast(float c) {
    unsigned int u = __float_as_uint(c);
    return ((f2)u << 32) | (f2)u;
}

// p_lo/p_hi = packed centers; h_lo/h_hi = packed 3-wide horizontal sums
__device__ __forceinline__ void hsum(const float4& m, float l, float r,
                                     f2& p_lo, f2& p_hi, f2& h_lo, f2& h_hi) {
    p_lo = pk(m.x, m.y);
    p_hi = pk(m.z, m.w);
    f2 A = pk(l,   m.x);
    f2 C = pk(m.y, m.z);
    f2 E = pk(m.w, r);
    h_lo = add2(add2(A, p_lo), C);
    h_hi = add2(add2(C, p_hi), E);
}

__device__ __forceinline__ f2 rule2(f2 cell, f2 H3,
                                    f2 C5, f2 Cm75, f2 C10, f2 C025) {
    f2 ar = sub2(H3, cell);          // around
    f2 a1 = fma2(ar, C5, Cm75);      //  5a - 7.5
    f2 a2 = sub2(C10, a1);           // 17.5 - 5a
    f2 a3 = sub2(a1, C5);            //  5a - 12.5
    float xa, xb;
    upk(xa, xb, a1); f2 t1 = pk(tanh_fast(xa), tanh_fast(xb));
    upk(xa, xb, a2); f2 t2 = pk(tanh_fast(xa), tanh_fast(xb));
    upk(xa, xb, a3); f2 t3 = pk(tanh_fast(xa), tanh_fast(xb));
    f2 d = sub2(t1, t3);
    f2 X = fma2(cell, d, t3);        // t3 + cell*(t1-t3)
    f2 f = fma2(t2, C025, C025);     // 0.25*(1+t2)
    return fma2(X, f, f);            // f*(1+X)
}

__global__ __launch_bounds__(128, 12)
void ContinuousGameOfLife_kernel(const float* __restrict__ x,
                                 float* __restrict__ out) {
    const int W = GOL_W, H = GOL_H;

    const int xb = blockIdx.x * blockDim.x + threadIdx.x;   // 0 .. W/4-1
    const int x4 = xb * 4;
    const int y0 = blockIdx.y * ROWS_PER_THREAD;
    const int b  = blockIdx.z;

    const float* __restrict__ base  = x   + (size_t)b * H * W;
    float*       __restrict__ obase = out + (size_t)b * H * W;

    const int xl = (x4 == 0)     ? (W - 1) : (x4 - 1);
    const int xr = (x4 + 4 == W) ? 0       : (x4 + 4);

    const f2 C5   = bcast(5.0f);
    const f2 Cm75 = bcast(-7.5f);
    const f2 C10  = bcast(10.0f);
    const f2 C025 = bcast(0.25f);

    // ---- prologue: rows y0-1, y0, y0+1 (batched -> MLP) ----
    const int ym = (y0 == 0) ? (H - 1) : (y0 - 1);
    const float* rp0 = base + (size_t)ym * W;
    const float* rp1 = base + (size_t)y0 * W;
    const float* rp2 = base + (size_t)(y0 + 1) * W;
    float4 m0 = *reinterpret_cast<const float4*>(rp0 + x4);
    float4 m1 = *reinterpret_cast<const float4*>(rp1 + x4);
    float4 m2 = *reinterpret_cast<const float4*>(rp2 + x4);
    float l0 = rp0[xl], r0 = rp0[xr];
    float l1 = rp1[xl], r1 = rp1[xr];
    float l2 = rp2[xl], r2 = rp2[xr];

    f2 tmp0, tmp1;
    f2 hP_lo, hP_hi, hC_lo, hC_hi, hN_lo, hN_hi;   // h window rows y-1, y, y+1
    f2 pC_lo, pC_hi, pN_lo, pN_hi;                 // cell packs rows y, y+1
    hsum(m0, l0, r0, tmp0,  tmp1,  hP_lo, hP_hi);
    hsum(m1, l1, r1, pC_lo, pC_hi, hC_lo, hC_hi);
    hsum(m2, l2, r2, pN_lo, pN_hi, hN_lo, hN_hi);

    // ---- main loop: all but last row (prefetch row y+2, fold for next iter) ----
    #pragma unroll
    for (int i = 0; i < ROWS_PER_THREAD - 1; ++i) {
        const int y = y0 + i;

        int yn2 = y + 2; if (yn2 >= H) yn2 -= H;
        const float* rpf = base + (size_t)yn2 * W;
        float4 mf = *reinterpret_cast<const float4*>(rpf + x4);
        float lf = rpf[xl], rf = rpf[xr];

        f2 H3_lo = add2(add2(hP_lo, hC_lo), hN_lo);
        f2 H3_hi = add2(add2(hP_hi, hC_hi), hN_hi);
        f2 o_lo = rule2(pC_lo, H3_lo, C5, Cm75, C10, C025);
        f2 o_hi = rule2(pC_hi, H3_hi, C5, Cm75, C10, C025);

        float4 o;
        upk(o.x, o.y, o_lo);
        upk(o.z, o.w, o_hi);
        __stcs(reinterpret_cast<float4*>(obase + (size_t)y * W + x4), o);

        hP_lo = hC_lo; hP_hi = hC_hi;
        hC_lo = hN_lo; hC_hi = hN_hi;
        pC_lo = pN_lo; pC_hi = pN_hi;
        hsum(mf, lf, rf, pN_lo, pN_hi, hN_lo, hN_hi);
    }

    // ---- peeled last row: compute-only, no dead prefetch/fold ----
    {
        const int y = y0 + ROWS_PER_THREAD - 1;
        f2 H3_lo = add2(add2(hP_lo, hC_lo), hN_lo);
        f2 H3_hi = add2(add2(hP_hi, hC_hi), hN_hi);
        f2 o_lo = rule2(pC_lo, H3_lo, C5, Cm75, C10, C025);
        f2 o_hi = rule2(pC_hi, H3_hi, C5, Cm75, C10, C025);

        float4 o;
        upk(o.x, o.y, o_lo);
        upk(o.z, o.w, o_hi);
        __stcs(reinterpret_cast<float4*>(obase + (size_t)y * W + x4), o);
    }
}

extern "C" void kernel_launch(void* const* d_in, const int* in_sizes, int n_in,
                              void* d_out, int out_size) {
    const float* x = (const float*)d_in[0];
    float* out = (float*)d_out;

    const int B = 16;
    dim3 block(128, 1, 1);
    dim3 grid((GOL_W / 4) / 128, GOL_H / ROWS_PER_THREAD, B);
    ContinuousGameOfLife_kernel<<<grid, block>>>(x, out);
}